// round 15
// baseline (speedup 1.0000x reference)
#include <cuda_runtime.h>
#include <cuda_fp16.h>
#include <math.h>
#include <stdint.h>

#define Bb   256
#define Tt   256
#define Hh   1024
#define Zz   1026
#define KW   1028

#define ZF_OFF   ((long long)Bb * Tt * Zz)
#define CZF_OFF  (ZF_OFF + (long long)Bb * Zz)
#define COEF_OFF (CZF_OFF + (long long)Bb * Zz)
#define MATS_OFF (COEF_OFF + (long long)Bb * Tt * 2)

// Persistent device state
__device__ float g_h[Bb * Hh];
__device__ float g_c[Bb * Hh];
__device__ float g_x[Bb * 2];
__device__ __align__(16) float g_salpha[2][Bb * 4];   // parity cumulative sums
// fp16 pre-swizzled images (8KB blocks: 64 rows x 64 k, 128B rows, SW128):
__device__ __align__(128) __half g_Wimg[64 * 16 * 4096];       // [nb][ch]
__device__ __align__(128) __half g_Aimg[2 * 4 * 16 * 4096];    // [par][mt][ch]
__device__ float g_bias[4096];
__device__ float g_wfront[4096 * 4];
// fine-grained sync: each flag on its own 128B line; cumulative, never reset
__device__ __align__(128) unsigned g_flag[2][16][32];   // [mb][ch][pad]
__device__ __align__(128) unsigned g_alpha_cnt;

__device__ __forceinline__ float fsigm(float x) {
    float e, r;
    asm("ex2.approx.f32 %0, %1;" : "=f"(e) : "f"(x * -1.442695041f));
    asm("rcp.approx.f32 %0, %1;" : "=f"(r) : "f"(1.0f + e));
    return r;
}
__device__ __forceinline__ float ftanh(float x) {
    return fmaf(2.0f, fsigm(2.0f * x), -1.0f);
}

__device__ __forceinline__ uint32_t smem_u32(const void* p) {
    uint32_t a;
    asm("{ .reg .u64 t; cvta.to.shared.u64 t, %1; cvt.u32.u64 %0, t; }" : "=r"(a) : "l"(p));
    return a;
}

__device__ __forceinline__ void ldsm4(uint32_t* r, uint32_t addr) {
    asm volatile("ldmatrix.sync.aligned.m8n8.x4.shared.b16 {%0,%1,%2,%3}, [%4];"
                 : "=r"(r[0]), "=r"(r[1]), "=r"(r[2]), "=r"(r[3]) : "r"(addr));
}

__device__ __forceinline__ void mma16816(float (&d)[4], const uint32_t* a,
                                         uint32_t b0, uint32_t b1) {
    asm volatile(
        "mma.sync.aligned.m16n8k16.row.col.f32.f16.f16.f32 "
        "{%0,%1,%2,%3}, {%4,%5,%6,%7}, {%8,%9}, {%0,%1,%2,%3};"
        : "+f"(d[0]), "+f"(d[1]), "+f"(d[2]), "+f"(d[3])
        : "r"(a[0]), "r"(a[1]), "r"(a[2]), "r"(a[3]), "r"(b0), "r"(b1));
}

#define CPA(dst, src) \
    asm volatile("cp.async.cg.shared.global [%0], [%1], 16;" \
                 :: "r"(dst), "l"(src) : "memory")
#define CPA_COMMIT() asm volatile("cp.async.commit_group;" ::: "memory")
#define CPA_WAIT0()  asm volatile("cp.async.wait_group 0;" ::: "memory")
#define CPA_WAIT3()  asm volatile("cp.async.wait_group 3;" ::: "memory")

__device__ __forceinline__ void poll_ge(const unsigned* addr, unsigned tgt) {
    unsigned v;
    do {
        asm volatile("ld.acquire.gpu.global.u32 %0, [%1];" : "=r"(v) : "l"(addr));
        if (v >= tgt) return;
        __nanosleep(16);
    } while (1);
}

// SMEM layout
#define SM_B    0        // 131072: resident B
#define SM_A    131072   // 65536: per-warp rings (4 warps x 4 x 4KB); D overlays own ring
#define SM_C    196608   // 10240: c state (128 x stride 20)
#define SM_MISC 206848   // 1536: bias | wfront | aw
#define SM_SX   208384   // 1024: x state
#define SM_PREV 209408   // 4096: prev cumulative salpha, 2 parities x 128 x 4
#define SM_TOT  213504
#define CSTRIDE 20
#define DW      68

// ---------------------------------------------------------------------------
__global__ void repack(const float* __restrict__ WU_w) {
    int nb = blockIdx.x, ch = blockIdx.y;
    char* base = (char*)g_Wimg + ((size_t)(nb * 16 + ch) << 13);
    for (int e = threadIdx.x; e < 4096; e += 256) {
        int r = e >> 6, c = e & 63;
        int rg = nb * 64 + r;
        int u = rg >> 2, g = rg & 3;
        float w = WU_w[(size_t)(g * Hh + u) * KW + 4 + ch * 64 + c];
        uint32_t off = (uint32_t)(r * 128 + c * 2);
        off ^= (off >> 3) & 0x70;
        *(__half*)(base + off) = __float2half_rn(w);
    }
}

__global__ void prep_misc(const float* __restrict__ WU_w,
                          const float* __restrict__ WU_b) {
    int r = blockIdx.x * 256 + threadIdx.x;
    if (r >= 4096) return;
    int u = r >> 2, g = r & 3;
    g_bias[r] = WU_b[g * Hh + u];
    const float* src = WU_w + (size_t)(g * Hh + u) * KW;
    #pragma unroll
    for (int j = 0; j < 4; j++) g_wfront[r * 4 + j] = src[j];
}

__global__ void init_state(const float* __restrict__ z0,
                           const float* __restrict__ c_z0) {
    int i = blockIdx.x * blockDim.x + threadIdx.x;
    if (i == 0) g_alpha_cnt = 0u;
    if (i < 1024) ((unsigned*)g_flag)[i] = 0u;
    if (i < Bb * 4) { g_salpha[0][i] = 0.0f; g_salpha[1][i] = 0.0f; }
    if (i < Bb * Hh) {
        int b = i / Hh, j = i - b * Hh;
        float hv = z0[(size_t)b * Zz + 2 + j];
        g_c[i] = c_z0[(size_t)b * Zz + 2 + j];
        int mt = b >> 6, row = b & 63, ch = j >> 6, kc = j & 63;
        uint32_t rel = (uint32_t)(row * 128 + kc * 2);
        rel ^= (rel >> 3) & 0x70;
        *(__half*)((char*)g_Aimg + ((size_t)(mt * 16 + ch) << 13) + rel)
            = __float2half_rn(hv);
    }
    if (i < Bb * 2) {
        int b = i >> 1, s = i & 1;
        g_x[i] = z0[(size_t)b * Zz + s];
    }
}

// stage one 4KB A slice: warp w's 32 rows of chunk ch into ring stage s
__device__ __forceinline__ void stage_w(int par, int mb, int w, int lane,
                                        uint32_t wring, int ch, int s) {
    const char* src = (const char*)g_Aimg
        + ((size_t)((par * 4 + mb * 2 + (w >> 1)) * 16 + ch) << 13)
        + (uint32_t)((w & 1) * 4096);
    uint32_t d = wring + (uint32_t)(s * 4096);
    #pragma unroll
    for (int i = 0; i < 8; i++) {
        uint32_t f = (uint32_t)((i * 32 + lane) * 16);
        CPA(d + f, src + f);
    }
}

// x dynamics update for step ts (reads parity buffer ts&1)
__device__ __forceinline__ void x_step(
    int ts, int b, int li, float* sx, float* sprev,
    const float* __restrict__ rnn_input, const float* __restrict__ tau,
    float ab0, float ab1, float wb0, float wb1,
    bool writer, float* __restrict__ out)
{
    int pb = ts & 1;
    float4 C = __ldcg((const float4*)(&g_salpha[pb][b * 4]));
    float4 P = *(float4*)(sprev + pb * 512 + li * 4);
    *(float4*)(sprev + pb * 512 + li * 4) = C;
    float s0 = C.x - P.x, s1 = C.y - P.y;
    float s2 = C.z - P.z, s3 = C.w - P.w;

    float x1 = sx[li * 2], x2 = sx[li * 2 + 1];
    float u  = rnn_input[(size_t)b * Tt * 2 + (size_t)ts * 2];
    float ta = tau[(size_t)b * Tt + ts];
    float a10 = -1.0f - 2.0f * x1 * x2;
    float a11 = 1.0f - x1 * x1;
    float xm0 = x1 + ta * x2;
    float xm1 = x2 + ta * (a10 * x1 + a11 * x2 + u);
    float al0 = fsigm(s0 + ab0);
    float al1 = fsigm(s1 + ab1);
    float xn0 = (1.0f - al0) * xm0 + al0 * (s2 + wb0);
    float xn1 = (1.0f - al1) * xm1 + al1 * (s3 + wb1);
    sx[li * 2]     = xn0;
    sx[li * 2 + 1] = xn1;

    if (writer) {
        size_t ob = (size_t)b * Tt * Zz + (size_t)ts * Zz;
        out[ob + 0] = xn0;
        out[ob + 1] = xn1;
        size_t cb = COEF_OFF + (size_t)b * Tt * 2 + (size_t)ts * 2;
        out[cb + 0] = al0;
        out[cb + 1] = al1;
        if (b == 0) {
            size_t mo = MATS_OFF + (size_t)ts * 4;
            out[mo + 0] = 0.0f;
            out[mo + 1] = 1.0f;
            out[mo + 2] = a10;
            out[mo + 3] = a11;
        }
        if (ts == Tt - 1) {
            g_x[b * 2 + 0] = xn0;
            g_x[b * 2 + 1] = xn1;
        }
    }
}

// ---------------------------------------------------------------------------
// Persistent kernel: grid 128 (mb = cta&1, nb = cta>>1), block 128 (4 warps)
// Warp tile m32 x n64. Fine-grained producer/consumer flags, no global barrier.
// ---------------------------------------------------------------------------
__global__ __launch_bounds__(128) void lstm_persist(
    const float* __restrict__ rnn_input, const float* __restrict__ tau,
    const float* __restrict__ alpha_w,   const float* __restrict__ alpha_b,
    const float* __restrict__ Wx_w,      const float* __restrict__ Wx_b,
    float* __restrict__ out)
{
    extern __shared__ char smraw[];
    uint32_t sb0 = smem_u32(smraw);
    uint32_t pad = (1024u - (sb0 & 1023u)) & 1023u;
    char* smb = smraw + pad;
    uint32_t sb = sb0 + pad;

    int tid = threadIdx.x;
    int cta = blockIdx.x;
    int mb = cta & 1, nb = cta >> 1;
    int m0 = mb * 128;
    int chme = nb >> 2;

    int w = tid >> 5, lane = tid & 31;
    uint32_t wring = sb + SM_A + ((uint32_t)w << 14);
    float* Dw = (float*)(smb + SM_A + (w << 14));
    uint32_t a_kx = (uint32_t)((lane >> 4) * 16);
    uint32_t a_xm = (uint32_t)((lane & 7) << 4);
    uint32_t a_ro = (uint32_t)((lane & 15) * 128);
    int brow = (lane & 7) + ((lane >> 4) & 1) * 8;
    uint32_t b_kx = (uint32_t)(((lane >> 3) & 1) * 16);
    uint32_t b_xm = (uint32_t)((lane & 7) << 4);

    float* sc    = (float*)(smb + SM_C);
    float* sbias = (float*)(smb + SM_MISC);
    float* swf   = sbias + 64;
    float* saw   = swf + 256;
    float* sx    = (float*)(smb + SM_SX);
    float* sprev = (float*)(smb + SM_PREV);

    // ---- prologue ----
    {
        const char* bsrc = (const char*)g_Wimg + ((size_t)(nb * 16) << 13);
        #pragma unroll
        for (int it = 0; it < 64; it++) {
            uint32_t f = (uint32_t)((it * 128 + tid) * 16);
            CPA(sb + SM_B + f, bsrc + f);
        }
        CPA_COMMIT();
        if (tid < 64)  sbias[tid] = g_bias[nb * 64 + tid];
        swf[tid]       = g_wfront[nb * 256 + tid];
        swf[tid + 128] = g_wfront[nb * 256 + 128 + tid];
        if (tid < 16) {
            saw[tid]      = alpha_w[nb * 16 + tid];
            saw[16 + tid] = alpha_w[1024 + nb * 16 + tid];
            saw[32 + tid] = Wx_w[nb * 16 + tid];
            saw[48 + tid] = Wx_w[1024 + nb * 16 + tid];
        }
        {
            const float* csrc = g_c + (size_t)(m0 + tid) * Hh + nb * 16;
            #pragma unroll
            for (int q = 0; q < 4; q++)
                *(float4*)(sc + tid * CSTRIDE + q * 4) = *(const float4*)(csrc + q * 4);
        }
        sx[tid * 2]     = g_x[(m0 + tid) * 2];
        sx[tid * 2 + 1] = g_x[(m0 + tid) * 2 + 1];
        *(float4*)(sprev + tid * 4)       = make_float4(0.f, 0.f, 0.f, 0.f);
        *(float4*)(sprev + 512 + tid * 4) = make_float4(0.f, 0.f, 0.f, 0.f);
        CPA_WAIT0();
        __syncthreads();
        stage_w(0, mb, w, lane, wring, 0, 0); CPA_COMMIT();
        stage_w(0, mb, w, lane, wring, 1, 1); CPA_COMMIT();
        stage_w(0, mb, w, lane, wring, 2, 2); CPA_COMMIT();
    }
    float ab0 = alpha_b[0], ab1 = alpha_b[1];
    float wb0 = Wx_b[0],    wb1 = Wx_b[1];

    for (int t = 0; t < Tt; t++) {
        int par = t & 1;

        float acc[2][8][4];
        #pragma unroll
        for (int s2 = 0; s2 < 2; s2++)
            #pragma unroll
            for (int j = 0; j < 8; j++)
                #pragma unroll
                for (int q = 0; q < 4; q++) acc[s2][j][q] = 0.0f;

        for (int c = 0; c < 16; c++) {
            if (c + 3 < 16) {
                if (lane == 0) poll_ge(&g_flag[mb][c + 3][0], 4u * (unsigned)t);
                __syncwarp();
                stage_w(par, mb, w, lane, wring, c + 3, (c + 3) & 3);
            }
            CPA_COMMIT();
            CPA_WAIT3();
            __syncwarp();
            uint32_t abb = wring + (uint32_t)((c & 3) * 4096) + a_ro;
            uint32_t bbb = sb + SM_B + ((uint32_t)c << 13);
            #pragma unroll
            for (int kk = 0; kk < 4; kk++) {
                uint32_t kofs = (uint32_t)(kk * 32);
                uint32_t axor = (a_kx + kofs) ^ a_xm;
                uint32_t A0[4], A1[4];
                ldsm4(A0, abb + axor);
                ldsm4(A1, abb + 2048 + axor);
                #pragma unroll
                for (int p = 0; p < 4; p++) {
                    uint32_t Bh[4];
                    ldsm4(Bh, bbb + (uint32_t)((p * 16 + brow) * 128)
                                  + ((b_kx + kofs) ^ b_xm));
                    mma16816(acc[0][2*p],     A0, Bh[0], Bh[1]);
                    mma16816(acc[0][2*p + 1], A0, Bh[2], Bh[3]);
                    mma16816(acc[1][2*p],     A1, Bh[0], Bh[1]);
                    mma16816(acc[1][2*p + 1], A1, Bh[2], Bh[3]);
                }
            }
        }
        CPA_WAIT0();
        __syncwarp();

        // D scratch in OWN ring (warp-local)
        {
            int rl = lane >> 2;
            int c0 = (lane & 3) * 2;
            #pragma unroll
            for (int s2 = 0; s2 < 2; s2++)
                #pragma unroll
                for (int j = 0; j < 8; j++) {
                    *(float2*)&Dw[(s2 * 16 + rl) * DW + j * 8 + c0] =
                        make_float2(acc[s2][j][0], acc[s2][j][1]);
                    *(float2*)&Dw[(s2 * 16 + rl + 8) * DW + j * 8 + c0] =
                        make_float2(acc[s2][j][2], acc[s2][j][3]);
                }
        }

        // x-update for step t-1 (parity-safe: see dependency argument)
        if (t > 0) {
            if (tid == 0) poll_ge(&g_alpha_cnt, 128u * (unsigned)t);
            __syncthreads();
            x_step(t - 1, m0 + tid, tid, sx, sprev, rnn_input, tau,
                   ab0, ab1, wb0, wb1, nb == 0, out);
        }
        __syncwarp();

        // ---- fused LSTM pointwise epilogue: thread -> 1 row, 16 units ----
        float hnv[16];
        {
            int row = tid;
            int b   = m0 + row;
            float xp0 = sx[row * 2], xp1 = sx[row * 2 + 1];
            const float* ibp = rnn_input + (size_t)b * Tt * 2 + (size_t)t * 2;
            float in0 = ibp[0], in1 = ibp[1];

            float* cp = sc + row * CSTRIDE;
            float cc[16];
            #pragma unroll
            for (int q = 0; q < 4; q++) {
                float4 v = *(float4*)(cp + q * 4);
                cc[4*q] = v.x; cc[4*q+1] = v.y; cc[4*q+2] = v.z; cc[4*q+3] = v.w;
            }
            float s0 = 0.f, s1 = 0.f, s2v = 0.f, s3 = 0.f;
            #pragma unroll
            for (int ul = 0; ul < 16; ul++) {
                float4 g4 = *(float4*)(&Dw[lane * DW + ul * 4]);
                float4 bias4 = *(float4*)(sbias + ul * 4);
                float gvv[4] = {g4.x + bias4.x, g4.y + bias4.y,
                                g4.z + bias4.z, g4.w + bias4.w};
                #pragma unroll
                for (int g2 = 0; g2 < 4; g2++) {
                    float4 wf = *(float4*)(swf + (ul * 4 + g2) * 4);
                    gvv[g2] += xp0 * wf.x + xp1 * wf.y + in0 * wf.z + in1 * wf.w;
                }
                float ig = fsigm(gvv[0]), fg = fsigm(gvv[1]);
                float gg = ftanh(gvv[2]), og = fsigm(gvv[3]);
                float cn = fg * cc[ul] + ig * gg;
                cc[ul] = cn;
                float hn = og * ftanh(cn);
                hnv[ul] = hn;
                s0  = fmaf(hn, saw[ul],      s0);
                s1  = fmaf(hn, saw[16 + ul], s1);
                s2v = fmaf(hn, saw[32 + ul], s2v);
                s3  = fmaf(hn, saw[48 + ul], s3);
            }
            #pragma unroll
            for (int q = 0; q < 4; q++)
                *(float4*)(cp + q * 4) = make_float4(cc[4*q], cc[4*q+1], cc[4*q+2], cc[4*q+3]);

            float* sa = g_salpha[par];
            atomicAdd(&sa[b * 4 + 0], s0);
            atomicAdd(&sa[b * 4 + 1], s1);
            atomicAdd(&sa[b * 4 + 2], s2v);
            atomicAdd(&sa[b * 4 + 3], s3);

            // next-step A image (fp16, pre-swizzled): 2 x 16B
            int mt = b >> 6, row64 = b & 63;
            char* ibase = (char*)g_Aimg
                        + ((size_t)(((par ^ 1) * 4 + mt) * 16 + chme) << 13);
            #pragma unroll
            for (int half = 0; half < 2; half++) {
                int kc = (nb & 3) * 16 + half * 8;
                uint32_t rel = (uint32_t)(row64 * 128)
                             + (((uint32_t)(kc * 2)) ^ ((row64 & 7) << 4));
                __half2 hx[4];
                #pragma unroll
                for (int j = 0; j < 4; j++)
                    hx[j] = __floats2half2_rn(hnv[half * 8 + 2*j], hnv[half * 8 + 2*j + 1]);
                *(uint4*)(ibase + rel) = *(uint4*)hx;
            }

            if (t == Tt - 1) {
                float* hp = g_h + (size_t)b * Hh + nb * 16;
                float* cg = g_c + (size_t)b * Hh + nb * 16;
                #pragma unroll
                for (int q = 0; q < 4; q++) {
                    *(float4*)(hp + q * 4) = make_float4(hnv[4*q], hnv[4*q+1], hnv[4*q+2], hnv[4*q+3]);
                    *(float4*)(cg + q * 4) = make_float4(cc[4*q], cc[4*q+1], cc[4*q+2], cc[4*q+3]);
                }
            }
        }

        // publish (A-image slice + alpha arrivals)
        __syncthreads();
        if (tid == 0) {
            __threadfence();
            asm volatile("red.release.gpu.global.add.u32 [%0], 1;"
                         :: "l"(&g_flag[mb][chme][0]) : "memory");
            asm volatile("red.release.gpu.global.add.u32 [%0], 1;"
                         :: "l"(&g_alpha_cnt) : "memory");
        }

        // external out stores (nothing depends on them)
        {
            int b = m0 + tid;
            float* op = out + (size_t)b * Tt * Zz + (size_t)t * Zz + 2 + nb * 16;
            #pragma unroll
            for (int q = 0; q < 8; q++)
                *(float2*)(op + q * 2) = make_float2(hnv[2*q], hnv[2*q+1]);
        }

        // prestage chunks 0..2 of step t+1 (lane-0 polls on 4-producer flags)
        if (t + 1 < Tt) {
            unsigned tgt = 4u * (unsigned)(t + 1);
            #pragma unroll
            for (int s = 0; s < 3; s++) {
                if (lane == 0) poll_ge(&g_flag[mb][s][0], tgt);
                __syncwarp();
                stage_w(par ^ 1, mb, w, lane, wring, s, s);
                CPA_COMMIT();
            }
        }
    }

    // final x-update (step Tt-1)
    if (tid == 0) poll_ge(&g_alpha_cnt, 128u * (unsigned)Tt);
    __syncthreads();
    x_step(Tt - 1, m0 + tid, tid, sx, sprev, rnn_input, tau,
           ab0, ab1, wb0, wb1, nb == 0, out);
}

// ---------------------------------------------------------------------------
__global__ void finalize(const float* __restrict__ c_z0,
                         float* __restrict__ out) {
    int i = blockIdx.x * blockDim.x + threadIdx.x;
    if (i >= Bb * Zz) return;
    int b = i / Zz, z = i - b * Zz;
    float zv, cv;
    if (z < 2) {
        zv = g_x[b * 2 + z];
        cv = c_z0[(size_t)b * Zz + z];
    } else {
        zv = g_h[(size_t)b * Hh + z - 2];
        cv = g_c[(size_t)b * Hh + z - 2];
    }
    out[ZF_OFF  + i] = zv;
    out[CZF_OFF + i] = cv;
}

// ---------------------------------------------------------------------------
extern "C" void kernel_launch(void* const* d_in, const int* in_sizes, int n_in,
                              void* d_out, int out_size) {
    const float* rnn_input = (const float*)d_in[0];
    const float* tau       = (const float*)d_in[1];
    const float* z0        = (const float*)d_in[2];
    const float* c_z0      = (const float*)d_in[3];
    const float* WU_w      = (const float*)d_in[4];
    const float* WU_b      = (const float*)d_in[5];
    const float* alpha_w   = (const float*)d_in[6];
    const float* alpha_b   = (const float*)d_in[7];
    const float* Wx_w      = (const float*)d_in[8];
    const float* Wx_b      = (const float*)d_in[9];
    float* out = (float*)d_out;

    const int smem_bytes = SM_TOT + 1024 + 128;   // 214656
    cudaFuncSetAttribute(lstm_persist,
                         cudaFuncAttributeMaxDynamicSharedMemorySize, smem_bytes);

    repack<<<dim3(64, 16), 256>>>(WU_w);
    prep_misc<<<16, 256>>>(WU_w, WU_b);
    init_state<<<(Bb * Hh + 255) / 256, 256>>>(z0, c_z0);

    lstm_persist<<<128, 128, smem_bytes>>>(rnn_input, tau, alpha_w, alpha_b,
                                           Wx_w, Wx_b, out);

    finalize<<<(Bb * Zz + 127) / 128, 128>>>(c_z0, out);
}

// round 16
// speedup vs baseline: 1.4057x; 1.4057x over previous
#include <cuda_runtime.h>
#include <cuda_fp16.h>
#include <math.h>
#include <stdint.h>

#define Bb   256
#define Tt   256
#define Hh   1024
#define Zz   1026
#define KW   1028

#define ZF_OFF   ((long long)Bb * Tt * Zz)
#define CZF_OFF  (ZF_OFF + (long long)Bb * Zz)
#define COEF_OFF (CZF_OFF + (long long)Bb * Zz)
#define MATS_OFF (COEF_OFF + (long long)Bb * Tt * 2)

// Persistent device state
__device__ float g_h[Bb * Hh];                       // final h (finalize only)
__device__ float g_c[Bb * Hh];                       // init + final c
__device__ float g_x[Bb * 2];                        // init + final x
__device__ __align__(16) float g_salpha[2][Bb * 4];  // parity cumulative sums
// fp16 pre-swizzled images (8KB blocks: 64 rows x 64 k, 128B rows, SW128):
__device__ __align__(128) __half g_Wimg[64 * 16 * 4096];       // [nb][ch]
__device__ __align__(128) __half g_Aimg[2 * 4 * 16 * 4096];    // [par][mt][ch]
__device__ float g_bias[4096];
__device__ float g_wfront[4096 * 4];
// grid barrier (cumulative counter, never reset)
__device__ unsigned g_bar_arrive;

// fast sigmoid/tanh via EX2+RCP (err ~1e-7, MUFU only)
__device__ __forceinline__ float fsigm(float x) {
    float e, r;
    asm("ex2.approx.f32 %0, %1;" : "=f"(e) : "f"(x * -1.442695041f));
    asm("rcp.approx.f32 %0, %1;" : "=f"(r) : "f"(1.0f + e));
    return r;
}
__device__ __forceinline__ float ftanh(float x) {
    return fmaf(2.0f, fsigm(2.0f * x), -1.0f);
}

__device__ __forceinline__ uint32_t smem_u32(const void* p) {
    uint32_t a;
    asm("{ .reg .u64 t; cvta.to.shared.u64 t, %1; cvt.u32.u64 %0, t; }" : "=r"(a) : "l"(p));
    return a;
}

__device__ __forceinline__ void ldsm4(uint32_t* r, uint32_t addr) {
    asm volatile("ldmatrix.sync.aligned.m8n8.x4.shared.b16 {%0,%1,%2,%3}, [%4];"
                 : "=r"(r[0]), "=r"(r[1]), "=r"(r[2]), "=r"(r[3]) : "r"(addr));
}

__device__ __forceinline__ void mma16816(float (&d)[4], const uint32_t* a,
                                         uint32_t b0, uint32_t b1) {
    asm volatile(
        "mma.sync.aligned.m16n8k16.row.col.f32.f16.f16.f32 "
        "{%0,%1,%2,%3}, {%4,%5,%6,%7}, {%8,%9}, {%0,%1,%2,%3};"
        : "+f"(d[0]), "+f"(d[1]), "+f"(d[2]), "+f"(d[3])
        : "r"(a[0]), "r"(a[1]), "r"(a[2]), "r"(a[3]), "r"(b0), "r"(b1));
}

#define CPA(dst, src) \
    asm volatile("cp.async.cg.shared.global [%0], [%1], 16;" \
                 :: "r"(dst), "l"(src) : "memory")
#define CPA_COMMIT() asm volatile("cp.async.commit_group;" ::: "memory")
#define CPA_WAIT0()  asm volatile("cp.async.wait_group 0;" ::: "memory")
#define CPA_WAIT3()  asm volatile("cp.async.wait_group 3;" ::: "memory")

// SMEM layout (relative to 1024-aligned base)
#define SM_B    0        // 131072: resident B (16 x 8KB)
#define SM_A    131072   // 65536: per-warp rings (4 warps x 4 stages x 4KB)
#define SM_C    196608   // 10240: c state (128 rows x stride 20)
#define SM_MISC 206848   // 1536: bias | wfront | aw
#define SM_SX   208384   // 1024: x state (128 x 2)
#define SM_PREV 209408   // 4096: prev cumulative salpha, 2 parities x 128 x 4
#define SM_TOT  213504
#define CSTRIDE 20
#define DW      68       // D row stride (floats)

// ---------------------------------------------------------------------------
__global__ void repack(const float* __restrict__ WU_w) {
    int nb = blockIdx.x, ch = blockIdx.y;
    char* base = (char*)g_Wimg + ((size_t)(nb * 16 + ch) << 13);
    for (int e = threadIdx.x; e < 4096; e += 256) {
        int r = e >> 6, c = e & 63;
        int rg = nb * 64 + r;
        int u = rg >> 2, g = rg & 3;
        float w = WU_w[(size_t)(g * Hh + u) * KW + 4 + ch * 64 + c];
        uint32_t off = (uint32_t)(r * 128 + c * 2);
        off ^= (off >> 3) & 0x70;
        *(__half*)(base + off) = __float2half_rn(w);
    }
}

__global__ void prep_misc(const float* __restrict__ WU_w,
                          const float* __restrict__ WU_b) {
    int r = blockIdx.x * 256 + threadIdx.x;
    if (r >= 4096) return;
    int u = r >> 2, g = r & 3;
    g_bias[r] = WU_b[g * Hh + u];
    const float* src = WU_w + (size_t)(g * Hh + u) * KW;
    #pragma unroll
    for (int j = 0; j < 4; j++) g_wfront[r * 4 + j] = src[j];
}

__global__ void init_state(const float* __restrict__ z0,
                           const float* __restrict__ c_z0) {
    int i = blockIdx.x * blockDim.x + threadIdx.x;
    if (i == 0) g_bar_arrive = 0u;
    if (i < Bb * 4) { g_salpha[0][i] = 0.0f; g_salpha[1][i] = 0.0f; }
    if (i < Bb * Hh) {
        int b = i / Hh, j = i - b * Hh;
        float hv = z0[(size_t)b * Zz + 2 + j];
        g_c[i] = c_z0[(size_t)b * Zz + 2 + j];
        int mt = b >> 6, row = b & 63, ch = j >> 6, kc = j & 63;
        uint32_t rel = (uint32_t)(row * 128 + kc * 2);
        rel ^= (rel >> 3) & 0x70;
        *(__half*)((char*)g_Aimg + ((size_t)(mt * 16 + ch) << 13) + rel)
            = __float2half_rn(hv);
    }
    if (i < Bb * 2) {
        int b = i >> 1, s = i & 1;
        g_x[i] = z0[(size_t)b * Zz + s];
    }
}

// stage one 4KB A slice: warp w's 32 rows of chunk ch into ring stage s
__device__ __forceinline__ void stage_w(int par, int mb, int w, int lane,
                                        uint32_t wring, int ch, int s) {
    const char* src = (const char*)g_Aimg
        + ((size_t)((par * 4 + mb * 2 + (w >> 1)) * 16 + ch) << 13)
        + (uint32_t)((w & 1) * 4096);
    uint32_t d = wring + (uint32_t)(s * 4096);
    #pragma unroll
    for (int i = 0; i < 8; i++) {
        uint32_t f = (uint32_t)((i * 32 + lane) * 16);
        CPA(d + f, src + f);
    }
}

// thread-local x dynamics update for step ts (consumes preloaded cumulative C)
__device__ __forceinline__ void x_step_compute(
    int ts, int b, int li, float4 C, float* sx, float* sprev,
    const float* __restrict__ rnn_input, const float* __restrict__ tau,
    float ab0, float ab1, float wb0, float wb1,
    bool writer, float* __restrict__ out)
{
    int pb = ts & 1;
    float4 P = *(float4*)(sprev + pb * 512 + li * 4);
    *(float4*)(sprev + pb * 512 + li * 4) = C;
    float s0 = C.x - P.x, s1 = C.y - P.y;
    float s2 = C.z - P.z, s3 = C.w - P.w;

    float x1 = sx[li * 2], x2 = sx[li * 2 + 1];
    float u  = rnn_input[(size_t)b * Tt * 2 + (size_t)ts * 2];
    float ta = tau[(size_t)b * Tt + ts];
    float a10 = -1.0f - 2.0f * x1 * x2;
    float a11 = 1.0f - x1 * x1;
    float xm0 = x1 + ta * x2;
    float xm1 = x2 + ta * (a10 * x1 + a11 * x2 + u);
    float al0 = fsigm(s0 + ab0);
    float al1 = fsigm(s1 + ab1);
    float xn0 = (1.0f - al0) * xm0 + al0 * (s2 + wb0);
    float xn1 = (1.0f - al1) * xm1 + al1 * (s3 + wb1);
    sx[li * 2]     = xn0;
    sx[li * 2 + 1] = xn1;

    if (writer) {
        size_t ob = (size_t)b * Tt * Zz + (size_t)ts * Zz;
        out[ob + 0] = xn0;
        out[ob + 1] = xn1;
        size_t cb = COEF_OFF + (size_t)b * Tt * 2 + (size_t)ts * 2;
        out[cb + 0] = al0;
        out[cb + 1] = al1;
        if (b == 0) {
            size_t mo = MATS_OFF + (size_t)ts * 4;
            out[mo + 0] = 0.0f;
            out[mo + 1] = 1.0f;
            out[mo + 2] = a10;
            out[mo + 3] = a11;
        }
        if (ts == Tt - 1) {
            g_x[b * 2 + 0] = xn0;
            g_x[b * 2 + 1] = xn1;
        }
    }
}

// ---------------------------------------------------------------------------
// Persistent kernel: grid 128 (mb = cta&1, nb = cta>>1), block 128 (4 warps)
// Warp tile m32 x n64. One-hop barrier; x-update fully thread-local & hoisted.
// ---------------------------------------------------------------------------
__global__ __launch_bounds__(128) void lstm_persist(
    const float* __restrict__ rnn_input, const float* __restrict__ tau,
    const float* __restrict__ alpha_w,   const float* __restrict__ alpha_b,
    const float* __restrict__ Wx_w,      const float* __restrict__ Wx_b,
    float* __restrict__ out)
{
    extern __shared__ char smraw[];
    uint32_t sb0 = smem_u32(smraw);
    uint32_t pad = (1024u - (sb0 & 1023u)) & 1023u;
    char* smb = smraw + pad;
    uint32_t sb = sb0 + pad;

    int tid = threadIdx.x;
    int cta = blockIdx.x;
    int mb = cta & 1, nb = cta >> 1;
    int m0 = mb * 128;

    int w = tid >> 5, lane = tid & 31;
    uint32_t wring = sb + SM_A + ((uint32_t)w << 14);   // 16KB ring per warp
    float* Dw = (float*)(smb + SM_A + (w << 14));
    uint32_t a_kx = (uint32_t)((lane >> 4) * 16);
    uint32_t a_xm = (uint32_t)((lane & 7) << 4);
    uint32_t a_ro = (uint32_t)((lane & 15) * 128);
    int brow = (lane & 7) + ((lane >> 4) & 1) * 8;
    uint32_t b_kx = (uint32_t)(((lane >> 3) & 1) * 16);
    uint32_t b_xm = (uint32_t)((lane & 7) << 4);

    float* sc    = (float*)(smb + SM_C);
    float* sbias = (float*)(smb + SM_MISC);
    float* swf   = sbias + 64;
    float* saw   = swf + 256;
    float* sx    = (float*)(smb + SM_SX);
    float* sprev = (float*)(smb + SM_PREV);

    // ---- prologue ----
    {
        const char* bsrc = (const char*)g_Wimg + ((size_t)(nb * 16) << 13);
        #pragma unroll
        for (int it = 0; it < 64; it++) {
            uint32_t f = (uint32_t)((it * 128 + tid) * 16);
            CPA(sb + SM_B + f, bsrc + f);
        }
        CPA_COMMIT();
        if (tid < 64)  sbias[tid] = g_bias[nb * 64 + tid];
        swf[tid]       = g_wfront[nb * 256 + tid];
        swf[tid + 128] = g_wfront[nb * 256 + 128 + tid];
        if (tid < 16) {
            saw[tid]      = alpha_w[nb * 16 + tid];
            saw[16 + tid] = alpha_w[1024 + nb * 16 + tid];
            saw[32 + tid] = Wx_w[nb * 16 + tid];
            saw[48 + tid] = Wx_w[1024 + nb * 16 + tid];
        }
        {
            const float* csrc = g_c + (size_t)(m0 + tid) * Hh + nb * 16;
            #pragma unroll
            for (int q = 0; q < 4; q++)
                *(float4*)(sc + tid * CSTRIDE + q * 4) = *(const float4*)(csrc + q * 4);
        }
        sx[tid * 2]     = g_x[(m0 + tid) * 2];
        sx[tid * 2 + 1] = g_x[(m0 + tid) * 2 + 1];
        *(float4*)(sprev + tid * 4)       = make_float4(0.f, 0.f, 0.f, 0.f);
        *(float4*)(sprev + 512 + tid * 4) = make_float4(0.f, 0.f, 0.f, 0.f);
        CPA_WAIT0();
        __syncthreads();
        stage_w(0, mb, w, lane, wring, 0, 0); CPA_COMMIT();
        stage_w(0, mb, w, lane, wring, 1, 1); CPA_COMMIT();
        stage_w(0, mb, w, lane, wring, 2, 2); CPA_COMMIT();
    }
    float ab0 = alpha_b[0], ab1 = alpha_b[1];
    float wb0 = Wx_b[0],    wb1 = Wx_b[1];

    for (int t = 0; t < Tt; t++) {
        int par = t & 1;

        // Preload step-(t-1) cumulative alpha sums; consumed pre-epilogue.
        // (Atomics for parity (t-1)&1 completed before barrier t-1, which we
        //  passed. No other CTA can be in epilogue t+1 touching this parity
        //  until we arrive at barrier t.)
        float4 xC;
        if (t > 0)
            xC = __ldcg((const float4*)(&g_salpha[(t - 1) & 1][(m0 + tid) * 4]));

        float acc[2][8][4];
        #pragma unroll
        for (int s2 = 0; s2 < 2; s2++)
            #pragma unroll
            for (int j = 0; j < 8; j++)
                #pragma unroll
                for (int q = 0; q < 4; q++) acc[s2][j][q] = 0.0f;

        for (int c = 0; c < 16; c++) {
            if (c + 3 < 16) stage_w(par, mb, w, lane, wring, c + 3, (c + 3) & 3);
            CPA_COMMIT();
            CPA_WAIT3();
            __syncwarp();
            uint32_t abb = wring + (uint32_t)((c & 3) * 4096) + a_ro;
            uint32_t bbb = sb + SM_B + ((uint32_t)c << 13);
            #pragma unroll
            for (int kk = 0; kk < 4; kk++) {
                uint32_t kofs = (uint32_t)(kk * 32);
                uint32_t axor = (a_kx + kofs) ^ a_xm;
                uint32_t A0[4], A1[4];
                ldsm4(A0, abb + axor);
                ldsm4(A1, abb + 2048 + axor);
                #pragma unroll
                for (int p = 0; p < 4; p++) {
                    uint32_t Bh[4];
                    ldsm4(Bh, bbb + (uint32_t)((p * 16 + brow) * 128)
                                  + ((b_kx + kofs) ^ b_xm));
                    mma16816(acc[0][2*p],     A0, Bh[0], Bh[1]);
                    mma16816(acc[0][2*p + 1], A0, Bh[2], Bh[3]);
                    mma16816(acc[1][2*p],     A1, Bh[0], Bh[1]);
                    mma16816(acc[1][2*p + 1], A1, Bh[2], Bh[3]);
                }
            }
        }
        CPA_WAIT0();
        __syncwarp();

        // D scratch in OWN ring (warp-local)
        {
            int rl = lane >> 2;
            int c0 = (lane & 3) * 2;
            #pragma unroll
            for (int s2 = 0; s2 < 2; s2++)
                #pragma unroll
                for (int j = 0; j < 8; j++) {
                    *(float2*)&Dw[(s2 * 16 + rl) * DW + j * 8 + c0] =
                        make_float2(acc[s2][j][0], acc[s2][j][1]);
                    *(float2*)&Dw[(s2 * 16 + rl + 8) * DW + j * 8 + c0] =
                        make_float2(acc[s2][j][2], acc[s2][j][3]);
                }
        }
        __syncwarp();

        // x-update for step t-1 (thread-local; LDG already in flight)
        if (t > 0)
            x_step_compute(t - 1, m0 + tid, tid, xC, sx, sprev,
                           rnn_input, tau, ab0, ab1, wb0, wb1, nb == 0, out);

        // ---- fused LSTM pointwise epilogue: thread -> 1 row, 16 units ----
        float hnv[16];
        {
            int row = tid;
            int b   = m0 + row;
            float xp0 = sx[row * 2], xp1 = sx[row * 2 + 1];
            const float* ibp = rnn_input + (size_t)b * Tt * 2 + (size_t)t * 2;
            float in0 = ibp[0], in1 = ibp[1];

            float* cp = sc + row * CSTRIDE;
            float cc[16];
            #pragma unroll
            for (int q = 0; q < 4; q++) {
                float4 v = *(float4*)(cp + q * 4);
                cc[4*q] = v.x; cc[4*q+1] = v.y; cc[4*q+2] = v.z; cc[4*q+3] = v.w;
            }
            float s0 = 0.f, s1 = 0.f, s2v = 0.f, s3 = 0.f;
            #pragma unroll
            for (int ul = 0; ul < 16; ul++) {
                float4 g4 = *(float4*)(&Dw[lane * DW + ul * 4]);
                float4 bias4 = *(float4*)(sbias + ul * 4);
                float gvv[4] = {g4.x + bias4.x, g4.y + bias4.y,
                                g4.z + bias4.z, g4.w + bias4.w};
                #pragma unroll
                for (int g2 = 0; g2 < 4; g2++) {
                    float4 wf = *(float4*)(swf + (ul * 4 + g2) * 4);
                    gvv[g2] += xp0 * wf.x + xp1 * wf.y + in0 * wf.z + in1 * wf.w;
                }
                float ig = fsigm(gvv[0]), fg = fsigm(gvv[1]);
                float gg = ftanh(gvv[2]), og = fsigm(gvv[3]);
                float cn = fg * cc[ul] + ig * gg;
                cc[ul] = cn;
                float hn = og * ftanh(cn);
                hnv[ul] = hn;
                s0  = fmaf(hn, saw[ul],      s0);
                s1  = fmaf(hn, saw[16 + ul], s1);
                s2v = fmaf(hn, saw[32 + ul], s2v);
                s3  = fmaf(hn, saw[48 + ul], s3);
            }
            #pragma unroll
            for (int q = 0; q < 4; q++)
                *(float4*)(cp + q * 4) = make_float4(cc[4*q], cc[4*q+1], cc[4*q+2], cc[4*q+3]);

            float* sa = g_salpha[par];
            atomicAdd(&sa[b * 4 + 0], s0);
            atomicAdd(&sa[b * 4 + 1], s1);
            atomicAdd(&sa[b * 4 + 2], s2v);
            atomicAdd(&sa[b * 4 + 3], s3);

            // next-step A image (fp16, pre-swizzled): 2 x 16B
            int mt = b >> 6, row64 = b & 63;
            int ch = nb >> 2;
            char* ibase = (char*)g_Aimg
                        + ((size_t)(((par ^ 1) * 4 + mt) * 16 + ch) << 13);
            #pragma unroll
            for (int half = 0; half < 2; half++) {
                int kc = (nb & 3) * 16 + half * 8;
                uint32_t rel = (uint32_t)(row64 * 128)
                             + (((uint32_t)(kc * 2)) ^ ((row64 & 7) << 4));
                __half2 hx[4];
                #pragma unroll
                for (int j = 0; j < 4; j++)
                    hx[j] = __floats2half2_rn(hnv[half * 8 + 2*j], hnv[half * 8 + 2*j + 1]);
                *(uint4*)(ibase + rel) = *(uint4*)hx;
            }

            if (t == Tt - 1) {
                float* hp = g_h + (size_t)b * Hh + nb * 16;
                float* cg = g_c + (size_t)b * Hh + nb * 16;
                #pragma unroll
                for (int q = 0; q < 4; q++) {
                    *(float4*)(hp + q * 4) = make_float4(hnv[4*q], hnv[4*q+1], hnv[4*q+2], hnv[4*q+3]);
                    *(float4*)(cg + q * 4) = make_float4(cc[4*q], cc[4*q+1], cc[4*q+2], cc[4*q+3]);
                }
            }
        }

        // ---- barrier arrive; out stores overlap the poll ----
        __syncthreads();
        if (tid == 0) {
            __threadfence();
            asm volatile("red.release.gpu.global.add.u32 [%0], 1;"
                         :: "l"(&g_bar_arrive) : "memory");
        }
        {   // external out stores: nothing depends on them
            int b = m0 + tid;
            float* op = out + (size_t)b * Tt * Zz + (size_t)t * Zz + 2 + nb * 16;
            #pragma unroll
            for (int q = 0; q < 8; q++)
                *(float2*)(op + q * 2) = make_float2(hnv[2*q], hnv[2*q+1]);
        }
        if (tid == 0) {
            unsigned tgt = 128u * (unsigned)(t + 1);
            unsigned v;
            do {
                asm volatile("ld.acquire.gpu.global.u32 %0, [%1];"
                             : "=r"(v) : "l"(&g_bar_arrive));
                if (v >= tgt) break;
                __nanosleep(16);
            } while (1);
        }
        __syncthreads();

        // prestage next step's first chunks (only post-barrier work)
        if (t + 1 < Tt) {
            stage_w(par ^ 1, mb, w, lane, wring, 0, 0); CPA_COMMIT();
            stage_w(par ^ 1, mb, w, lane, wring, 1, 1); CPA_COMMIT();
            stage_w(par ^ 1, mb, w, lane, wring, 2, 2); CPA_COMMIT();
        }
    }

    // final x-update (step Tt-1): all atomics done (we passed final barrier)
    {
        float4 xC = __ldcg((const float4*)(&g_salpha[(Tt - 1) & 1][(m0 + tid) * 4]));
        x_step_compute(Tt - 1, m0 + tid, tid, xC, sx, sprev,
                       rnn_input, tau, ab0, ab1, wb0, wb1, nb == 0, out);
    }
}

// ---------------------------------------------------------------------------
__global__ void finalize(const float* __restrict__ c_z0,
                         float* __restrict__ out) {
    int i = blockIdx.x * blockDim.x + threadIdx.x;
    if (i >= Bb * Zz) return;
    int b = i / Zz, z = i - b * Zz;
    float zv, cv;
    if (z < 2) {
        zv = g_x[b * 2 + z];
        cv = c_z0[(size_t)b * Zz + z];
    } else {
        zv = g_h[(size_t)b * Hh + z - 2];
        cv = g_c[(size_t)b * Hh + z - 2];
    }
    out[ZF_OFF  + i] = zv;
    out[CZF_OFF + i] = cv;
}

// ---------------------------------------------------------------------------
extern "C" void kernel_launch(void* const* d_in, const int* in_sizes, int n_in,
                              void* d_out, int out_size) {
    const float* rnn_input = (const float*)d_in[0];
    const float* tau       = (const float*)d_in[1];
    const float* z0        = (const float*)d_in[2];
    const float* c_z0      = (const float*)d_in[3];
    const float* WU_w      = (const float*)d_in[4];
    const float* WU_b      = (const float*)d_in[5];
    const float* alpha_w   = (const float*)d_in[6];
    const float* alpha_b   = (const float*)d_in[7];
    const float* Wx_w      = (const float*)d_in[8];
    const float* Wx_b      = (const float*)d_in[9];
    float* out = (float*)d_out;

    const int smem_bytes = SM_TOT + 1024 + 128;   // 214656
    cudaFuncSetAttribute(lstm_persist,
                         cudaFuncAttributeMaxDynamicSharedMemorySize, smem_bytes);

    repack<<<dim3(64, 16), 256>>>(WU_w);
    prep_misc<<<16, 256>>>(WU_w, WU_b);
    init_state<<<(Bb * Hh + 255) / 256, 256>>>(z0, c_z0);

    lstm_persist<<<128, 128, smem_bytes>>>(rnn_input, tau, alpha_w, alpha_b,
                                           Wx_w, Wx_b, out);

    finalize<<<(Bb * Zz + 127) / 128, 128>>>(c_z0, out);
}

// round 17
// speedup vs baseline: 1.4229x; 1.0122x over previous
#include <cuda_runtime.h>
#include <cuda_fp16.h>
#include <math.h>
#include <stdint.h>

#define Bb   256
#define Tt   256
#define Hh   1024
#define Zz   1026
#define KW   1028

#define ZF_OFF   ((long long)Bb * Tt * Zz)
#define CZF_OFF  (ZF_OFF + (long long)Bb * Zz)
#define COEF_OFF (CZF_OFF + (long long)Bb * Zz)
#define MATS_OFF (COEF_OFF + (long long)Bb * Tt * 2)

// Persistent device state
__device__ float g_h[Bb * Hh];
__device__ float g_c[Bb * Hh];
__device__ float g_x[Bb * 2];
__device__ __align__(16) float g_salpha[2][Bb * 4];  // parity cumulative sums
// fp16 pre-swizzled images (8KB blocks: 64 rows x 64 k, 128B rows, SW128):
__device__ __align__(128) __half g_Wimg[64 * 16 * 4096];       // [nb][ch]
__device__ __align__(128) __half g_Aimg[2 * 4 * 16 * 4096];    // [par][mt][ch]
__device__ float g_bias[4096];
__device__ float g_wfront[4096 * 4];
// per-mb grid barriers (cumulative, never reset, own 128B lines)
__device__ __align__(128) unsigned g_bar[2][32];

__device__ __forceinline__ float fsigm(float x) {
    float e, r;
    asm("ex2.approx.f32 %0, %1;" : "=f"(e) : "f"(x * -1.442695041f));
    asm("rcp.approx.f32 %0, %1;" : "=f"(r) : "f"(1.0f + e));
    return r;
}
__device__ __forceinline__ float ftanh(float x) {
    return fmaf(2.0f, fsigm(2.0f * x), -1.0f);
}

__device__ __forceinline__ uint32_t smem_u32(const void* p) {
    uint32_t a;
    asm("{ .reg .u64 t; cvta.to.shared.u64 t, %1; cvt.u32.u64 %0, t; }" : "=r"(a) : "l"(p));
    return a;
}

__device__ __forceinline__ void ldsm4(uint32_t* r, uint32_t addr) {
    asm volatile("ldmatrix.sync.aligned.m8n8.x4.shared.b16 {%0,%1,%2,%3}, [%4];"
                 : "=r"(r[0]), "=r"(r[1]), "=r"(r[2]), "=r"(r[3]) : "r"(addr));
}

__device__ __forceinline__ void mma16816(float (&d)[4], const uint32_t* a,
                                         uint32_t b0, uint32_t b1) {
    asm volatile(
        "mma.sync.aligned.m16n8k16.row.col.f32.f16.f16.f32 "
        "{%0,%1,%2,%3}, {%4,%5,%6,%7}, {%8,%9}, {%0,%1,%2,%3};"
        : "+f"(d[0]), "+f"(d[1]), "+f"(d[2]), "+f"(d[3])
        : "r"(a[0]), "r"(a[1]), "r"(a[2]), "r"(a[3]), "r"(b0), "r"(b1));
}

#define CPA(dst, src) \
    asm volatile("cp.async.cg.shared.global [%0], [%1], 16;" \
                 :: "r"(dst), "l"(src) : "memory")
#define CPA_COMMIT() asm volatile("cp.async.commit_group;" ::: "memory")
#define CPA_WAIT0()  asm volatile("cp.async.wait_group 0;" ::: "memory")
#define CPA_WAIT3()  asm volatile("cp.async.wait_group 3;" ::: "memory")

// SMEM layout (relative to 1024-aligned base)
#define SM_B    0        // 131072: resident B (16 x 8KB)
#define SM_A    131072   // 65536: MMA-warp rings (4 x 4 stages x 4KB); D overlays
#define SM_C    196608   // 10240: c state (128 rows x stride 20)
#define SM_MISC 206848   // 1536: bias | wfront | aw
#define SM_SX   208384   // 1024: x state (128 x 2)
#define SM_PREV 209408   // 4096: prev cumulative salpha, 2 parities x 128 x 4
#define SM_TOT  213504
#define CSTRIDE 20
#define DW      68       // D row stride (floats)

// ---------------------------------------------------------------------------
__global__ void repack(const float* __restrict__ WU_w) {
    int nb = blockIdx.x, ch = blockIdx.y;
    char* base = (char*)g_Wimg + ((size_t)(nb * 16 + ch) << 13);
    for (int e = threadIdx.x; e < 4096; e += 256) {
        int r = e >> 6, c = e & 63;
        int rg = nb * 64 + r;
        int u = rg >> 2, g = rg & 3;
        float w = WU_w[(size_t)(g * Hh + u) * KW + 4 + ch * 64 + c];
        uint32_t off = (uint32_t)(r * 128 + c * 2);
        off ^= (off >> 3) & 0x70;
        *(__half*)(base + off) = __float2half_rn(w);
    }
}

__global__ void prep_misc(const float* __restrict__ WU_w,
                          const float* __restrict__ WU_b) {
    int r = blockIdx.x * 256 + threadIdx.x;
    if (r >= 4096) return;
    int u = r >> 2, g = r & 3;
    g_bias[r] = WU_b[g * Hh + u];
    const float* src = WU_w + (size_t)(g * Hh + u) * KW;
    #pragma unroll
    for (int j = 0; j < 4; j++) g_wfront[r * 4 + j] = src[j];
}

__global__ void init_state(const float* __restrict__ z0,
                           const float* __restrict__ c_z0) {
    int i = blockIdx.x * blockDim.x + threadIdx.x;
    if (i < 64) g_bar[i >> 5][i & 31] = 0u;
    if (i < Bb * 4) { g_salpha[0][i] = 0.0f; g_salpha[1][i] = 0.0f; }
    if (i < Bb * Hh) {
        int b = i / Hh, j = i - b * Hh;
        float hv = z0[(size_t)b * Zz + 2 + j];
        g_c[i] = c_z0[(size_t)b * Zz + 2 + j];
        int mt = b >> 6, row = b & 63, ch = j >> 6, kc = j & 63;
        uint32_t rel = (uint32_t)(row * 128 + kc * 2);
        rel ^= (rel >> 3) & 0x70;
        *(__half*)((char*)g_Aimg + ((size_t)(mt * 16 + ch) << 13) + rel)
            = __float2half_rn(hv);
    }
    if (i < Bb * 2) {
        int b = i >> 1, s = i & 1;
        g_x[i] = z0[(size_t)b * Zz + s];
    }
}

// stage one 4KB A slice: MMA-warp w (0..3), 32 rows of chunk ch into stage s
__device__ __forceinline__ void stage_w(int par, int mb, int w, int lane,
                                        uint32_t wring, int ch, int s) {
    const char* src = (const char*)g_Aimg
        + ((size_t)((par * 4 + mb * 2 + (w >> 1)) * 16 + ch) << 13)
        + (uint32_t)((w & 1) * 4096);
    uint32_t d = wring + (uint32_t)(s * 4096);
    #pragma unroll
    for (int i = 0; i < 8; i++) {
        uint32_t f = (uint32_t)((i * 32 + lane) * 16);
        CPA(d + f, src + f);
    }
}

// thread-local x dynamics update for step ts
__device__ __forceinline__ void x_step_compute(
    int ts, int b, int li, float4 C, float* sx, float* sprev,
    const float* __restrict__ rnn_input, const float* __restrict__ tau,
    float ab0, float ab1, float wb0, float wb1,
    bool writer, float* __restrict__ out)
{
    int pb = ts & 1;
    float4 P = *(float4*)(sprev + pb * 512 + li * 4);
    *(float4*)(sprev + pb * 512 + li * 4) = C;
    float s0 = C.x - P.x, s1 = C.y - P.y;
    float s2 = C.z - P.z, s3 = C.w - P.w;

    float x1 = sx[li * 2], x2 = sx[li * 2 + 1];
    float u  = rnn_input[(size_t)b * Tt * 2 + (size_t)ts * 2];
    float ta = tau[(size_t)b * Tt + ts];
    float a10 = -1.0f - 2.0f * x1 * x2;
    float a11 = 1.0f - x1 * x1;
    float xm0 = x1 + ta * x2;
    float xm1 = x2 + ta * (a10 * x1 + a11 * x2 + u);
    float al0 = fsigm(s0 + ab0);
    float al1 = fsigm(s1 + ab1);
    float xn0 = (1.0f - al0) * xm0 + al0 * (s2 + wb0);
    float xn1 = (1.0f - al1) * xm1 + al1 * (s3 + wb1);
    sx[li * 2]     = xn0;
    sx[li * 2 + 1] = xn1;

    if (writer) {
        size_t ob = (size_t)b * Tt * Zz + (size_t)ts * Zz;
        out[ob + 0] = xn0;
        out[ob + 1] = xn1;
        size_t cb = COEF_OFF + (size_t)b * Tt * 2 + (size_t)ts * 2;
        out[cb + 0] = al0;
        out[cb + 1] = al1;
        if (b == 0) {
            size_t mo = MATS_OFF + (size_t)ts * 4;
            out[mo + 0] = 0.0f;
            out[mo + 1] = 1.0f;
            out[mo + 2] = a10;
            out[mo + 3] = a11;
        }
        if (ts == Tt - 1) {
            g_x[b * 2 + 0] = xn0;
            g_x[b * 2 + 1] = xn1;
        }
    }
}

// ---------------------------------------------------------------------------
// Persistent kernel: grid 128 (mb = cta&1, nb = cta>>1), block 256.
// Warps 0-3: m32n64 MMA mainloop. Warps 4-7: concurrent x-update, then all
// 8 warps share the epilogue (8 units/thread). Per-mb 64-CTA barriers.
// ---------------------------------------------------------------------------
__global__ __launch_bounds__(256) void lstm_persist(
    const float* __restrict__ rnn_input, const float* __restrict__ tau,
    const float* __restrict__ alpha_w,   const float* __restrict__ alpha_b,
    const float* __restrict__ Wx_w,      const float* __restrict__ Wx_b,
    float* __restrict__ out)
{
    extern __shared__ char smraw[];
    uint32_t sb0 = smem_u32(smraw);
    uint32_t pad = (1024u - (sb0 & 1023u)) & 1023u;
    char* smb = smraw + pad;
    uint32_t sb = sb0 + pad;

    int tid = threadIdx.x;
    int cta = blockIdx.x;
    int mb = cta & 1, nb = cta >> 1;
    int m0 = mb * 128;

    int w = tid >> 5, lane = tid & 31;
    bool mmaw = (w < 4);
    uint32_t wring = sb + SM_A + ((uint32_t)(w & 3) << 14);
    uint32_t a_kx = (uint32_t)((lane >> 4) * 16);
    uint32_t a_xm = (uint32_t)((lane & 7) << 4);
    uint32_t a_ro = (uint32_t)((lane & 15) * 128);
    int brow = (lane & 7) + ((lane >> 4) & 1) * 8;
    uint32_t b_kx = (uint32_t)(((lane >> 3) & 1) * 16);
    uint32_t b_xm = (uint32_t)((lane & 7) << 4);

    float* sc    = (float*)(smb + SM_C);
    float* sbias = (float*)(smb + SM_MISC);
    float* swf   = sbias + 64;
    float* saw   = swf + 256;
    float* sx    = (float*)(smb + SM_SX);
    float* sprev = (float*)(smb + SM_PREV);
    float* Dall  = (float*)(smb + SM_A);

    // ---- prologue ----
    {
        const char* bsrc = (const char*)g_Wimg + ((size_t)(nb * 16) << 13);
        #pragma unroll
        for (int it = 0; it < 32; it++) {
            uint32_t f = (uint32_t)((it * 256 + tid) * 16);
            CPA(sb + SM_B + f, bsrc + f);
        }
        CPA_COMMIT();
        if (tid < 64)  sbias[tid] = g_bias[nb * 64 + tid];
        if (tid < 256) swf[tid] = g_wfront[nb * 256 + tid];
        if (tid < 16) {
            saw[tid]      = alpha_w[nb * 16 + tid];
            saw[16 + tid] = alpha_w[1024 + nb * 16 + tid];
            saw[32 + tid] = Wx_w[nb * 16 + tid];
            saw[48 + tid] = Wx_w[1024 + nb * 16 + tid];
        }
        if (tid < 128) {
            const float* csrc = g_c + (size_t)(m0 + tid) * Hh + nb * 16;
            #pragma unroll
            for (int q = 0; q < 4; q++)
                *(float4*)(sc + tid * CSTRIDE + q * 4) = *(const float4*)(csrc + q * 4);
            sx[tid * 2]     = g_x[(m0 + tid) * 2];
            sx[tid * 2 + 1] = g_x[(m0 + tid) * 2 + 1];
            *(float4*)(sprev + tid * 4)       = make_float4(0.f, 0.f, 0.f, 0.f);
            *(float4*)(sprev + 512 + tid * 4) = make_float4(0.f, 0.f, 0.f, 0.f);
        }
        CPA_WAIT0();
        __syncthreads();
        if (mmaw) {
            stage_w(0, mb, w, lane, wring, 0, 0); CPA_COMMIT();
            stage_w(0, mb, w, lane, wring, 1, 1); CPA_COMMIT();
            stage_w(0, mb, w, lane, wring, 2, 2); CPA_COMMIT();
        }
    }
    float ab0 = alpha_b[0], ab1 = alpha_b[1];
    float wb0 = Wx_b[0],    wb1 = Wx_b[1];

    for (int t = 0; t < Tt; t++) {
        int par = t & 1;

        if (mmaw) {
            float acc[2][8][4];
            #pragma unroll
            for (int s2 = 0; s2 < 2; s2++)
                #pragma unroll
                for (int j = 0; j < 8; j++)
                    #pragma unroll
                    for (int q = 0; q < 4; q++) acc[s2][j][q] = 0.0f;

            for (int c = 0; c < 16; c++) {
                if (c + 3 < 16) stage_w(par, mb, w, lane, wring, c + 3, (c + 3) & 3);
                CPA_COMMIT();
                CPA_WAIT3();
                __syncwarp();
                uint32_t abb = wring + (uint32_t)((c & 3) * 4096) + a_ro;
                uint32_t bbb = sb + SM_B + ((uint32_t)c << 13);
                #pragma unroll
                for (int kk = 0; kk < 4; kk++) {
                    uint32_t kofs = (uint32_t)(kk * 32);
                    uint32_t axor = (a_kx + kofs) ^ a_xm;
                    uint32_t A0[4], A1[4];
                    ldsm4(A0, abb + axor);
                    ldsm4(A1, abb + 2048 + axor);
                    #pragma unroll
                    for (int p = 0; p < 4; p++) {
                        uint32_t Bh[4];
                        ldsm4(Bh, bbb + (uint32_t)((p * 16 + brow) * 128)
                                      + ((b_kx + kofs) ^ b_xm));
                        mma16816(acc[0][2*p],     A0, Bh[0], Bh[1]);
                        mma16816(acc[0][2*p + 1], A0, Bh[2], Bh[3]);
                        mma16816(acc[1][2*p],     A1, Bh[0], Bh[1]);
                        mma16816(acc[1][2*p + 1], A1, Bh[2], Bh[3]);
                    }
                }
            }
            CPA_WAIT0();
            __syncwarp();
            // D scratch in OWN ring
            float* Dw = Dall + ((w & 3) << 12);
            int rl = lane >> 2;
            int c0 = (lane & 3) * 2;
            #pragma unroll
            for (int s2 = 0; s2 < 2; s2++)
                #pragma unroll
                for (int j = 0; j < 8; j++) {
                    *(float2*)&Dw[(s2 * 16 + rl) * DW + j * 8 + c0] =
                        make_float2(acc[s2][j][0], acc[s2][j][1]);
                    *(float2*)&Dw[(s2 * 16 + rl + 8) * DW + j * 8 + c0] =
                        make_float2(acc[s2][j][2], acc[s2][j][3]);
                }
        } else {
            // helper warps: x-update for step t-1, concurrent with mainloop
            if (t > 0) {
                int li = tid - 128;
                float4 xC = __ldcg((const float4*)(&g_salpha[(t - 1) & 1][(m0 + li) * 4]));
                x_step_compute(t - 1, m0 + li, li, xC, sx, sprev,
                               rnn_input, tau, ab0, ab1, wb0, wb1, nb == 0, out);
            }
        }
        __syncthreads();   // D + sx ready for everyone

        // ---- epilogue: 256 threads, 8 units each ----
        float hnv[8];
        {
            int row = tid >> 1;
            int ub  = (tid & 1) * 8;
            int b   = m0 + row;
            float xp0 = sx[row * 2], xp1 = sx[row * 2 + 1];
            const float* ibp = rnn_input + (size_t)b * Tt * 2 + (size_t)t * 2;
            float in0 = ibp[0], in1 = ibp[1];

            const float* Dw = Dall + ((row >> 5) << 12) + (row & 31) * DW;
            float* cp = sc + row * CSTRIDE + ub;

            float cc[8];
            #pragma unroll
            for (int q = 0; q < 2; q++) {
                float4 v = *(float4*)(cp + q * 4);
                cc[4*q] = v.x; cc[4*q+1] = v.y; cc[4*q+2] = v.z; cc[4*q+3] = v.w;
            }
            float s0 = 0.f, s1 = 0.f, s2v = 0.f, s3 = 0.f;
            #pragma unroll
            for (int q = 0; q < 8; q++) {
                int ul = ub + q;
                float4 g4 = *(float4*)(&Dw[ul * 4]);
                float4 bias4 = *(float4*)(sbias + ul * 4);
                float gvv[4] = {g4.x + bias4.x, g4.y + bias4.y,
                                g4.z + bias4.z, g4.w + bias4.w};
                #pragma unroll
                for (int g2 = 0; g2 < 4; g2++) {
                    float4 wf = *(float4*)(swf + (ul * 4 + g2) * 4);
                    gvv[g2] += xp0 * wf.x + xp1 * wf.y + in0 * wf.z + in1 * wf.w;
                }
                float ig = fsigm(gvv[0]), fg = fsigm(gvv[1]);
                float gg = ftanh(gvv[2]), og = fsigm(gvv[3]);
                float cn = fg * cc[q] + ig * gg;
                cc[q] = cn;
                float hn = og * ftanh(cn);
                hnv[q] = hn;
                s0  = fmaf(hn, saw[ul],      s0);
                s1  = fmaf(hn, saw[16 + ul], s1);
                s2v = fmaf(hn, saw[32 + ul], s2v);
                s3  = fmaf(hn, saw[48 + ul], s3);
            }
            #pragma unroll
            for (int q = 0; q < 2; q++)
                *(float4*)(cp + q * 4) = make_float4(cc[4*q], cc[4*q+1], cc[4*q+2], cc[4*q+3]);

            // combine (tid, tid^1) partials, even thread atomics
            s0  += __shfl_xor_sync(0xffffffffu, s0, 1);
            s1  += __shfl_xor_sync(0xffffffffu, s1, 1);
            s2v += __shfl_xor_sync(0xffffffffu, s2v, 1);
            s3  += __shfl_xor_sync(0xffffffffu, s3, 1);
            if ((tid & 1) == 0) {
                float* sa = g_salpha[par];
                atomicAdd(&sa[b * 4 + 0], s0);
                atomicAdd(&sa[b * 4 + 1], s1);
                atomicAdd(&sa[b * 4 + 2], s2v);
                atomicAdd(&sa[b * 4 + 3], s3);
            }

            // next-step A image (fp16, pre-swizzled): one 16B write
            int mt = b >> 6, row64 = b & 63;
            int ch = nb >> 2;
            int kc = (nb & 3) * 16 + ub;
            uint32_t rel = (uint32_t)(row64 * 128)
                         + (((uint32_t)(kc * 2)) ^ ((row64 & 7) << 4));
            __half2 hx[4];
            #pragma unroll
            for (int j = 0; j < 4; j++)
                hx[j] = __floats2half2_rn(hnv[2*j], hnv[2*j+1]);
            char* idst = (char*)g_Aimg
                       + ((size_t)(((par ^ 1) * 4 + mt) * 16 + ch) << 13) + rel;
            *(uint4*)idst = *(uint4*)hx;

            if (t == Tt - 1) {
                float* hp = g_h + (size_t)b * Hh + nb * 16 + ub;
                float* cg = g_c + (size_t)b * Hh + nb * 16 + ub;
                #pragma unroll
                for (int q = 0; q < 2; q++) {
                    *(float4*)(hp + q * 4) = make_float4(hnv[4*q], hnv[4*q+1], hnv[4*q+2], hnv[4*q+3]);
                    *(float4*)(cg + q * 4) = make_float4(cc[4*q], cc[4*q+1], cc[4*q+2], cc[4*q+3]);
                }
            }
        }

        // ---- per-mb barrier arrive; out stores overlap the poll ----
        __syncthreads();
        if (tid == 0) {
            __threadfence();
            asm volatile("red.release.gpu.global.add.u32 [%0], 1;"
                         :: "l"(&g_bar[mb][0]) : "memory");
        }
        {   // external out stores: nothing depends on them
            int row = tid >> 1;
            int b   = m0 + row;
            float* op = out + (size_t)b * Tt * Zz + (size_t)t * Zz + 2
                      + nb * 16 + (tid & 1) * 8;
            #pragma unroll
            for (int q = 0; q < 4; q++)
                *(float2*)(op + q * 2) = make_float2(hnv[2*q], hnv[2*q+1]);
        }
        if (tid == 0) {
            unsigned tgt = 64u * (unsigned)(t + 1);
            unsigned v;
            do {
                asm volatile("ld.acquire.gpu.global.u32 %0, [%1];"
                             : "=r"(v) : "l"(&g_bar[mb][0]));
                if (v >= tgt) break;
                __nanosleep(16);
            } while (1);
        }
        __syncthreads();

        // prestage next step's first chunks (MMA warps only)
        if (mmaw && t + 1 < Tt) {
            stage_w(par ^ 1, mb, w, lane, wring, 0, 0); CPA_COMMIT();
            stage_w(par ^ 1, mb, w, lane, wring, 1, 1); CPA_COMMIT();
            stage_w(par ^ 1, mb, w, lane, wring, 2, 2); CPA_COMMIT();
        }
    }

    // final x-update (step Tt-1): atomics complete (passed final barrier)
    if (!mmaw) {
        int li = tid - 128;
        float4 xC = __ldcg((const float4*)(&g_salpha[(Tt - 1) & 1][(m0 + li) * 4]));
        x_step_compute(Tt - 1, m0 + li, li, xC, sx, sprev,
                       rnn_input, tau, ab0, ab1, wb0, wb1, nb == 0, out);
    }
}

// ---------------------------------------------------------------------------
__global__ void finalize(const float* __restrict__ c_z0,
                         float* __restrict__ out) {
    int i = blockIdx.x * blockDim.x + threadIdx.x;
    if (i >= Bb * Zz) return;
    int b = i / Zz, z = i - b * Zz;
    float zv, cv;
    if (z < 2) {
        zv = g_x[b * 2 + z];
        cv = c_z0[(size_t)b * Zz + z];
    } else {
        zv = g_h[(size_t)b * Hh + z - 2];
        cv = g_c[(size_t)b * Hh + z - 2];
    }
    out[ZF_OFF  + i] = zv;
    out[CZF_OFF + i] = cv;
}

// ---------------------------------------------------------------------------
extern "C" void kernel_launch(void* const* d_in, const int* in_sizes, int n_in,
                              void* d_out, int out_size) {
    const float* rnn_input = (const float*)d_in[0];
    const float* tau       = (const float*)d_in[1];
    const float* z0        = (const float*)d_in[2];
    const float* c_z0      = (const float*)d_in[3];
    const float* WU_w      = (const float*)d_in[4];
    const float* WU_b      = (const float*)d_in[5];
    const float* alpha_w   = (const float*)d_in[6];
    const float* alpha_b   = (const float*)d_in[7];
    const float* Wx_w      = (const float*)d_in[8];
    const float* Wx_b      = (const float*)d_in[9];
    float* out = (float*)d_out;

    const int smem_bytes = SM_TOT + 1024 + 128;   // 214656
    cudaFuncSetAttribute(lstm_persist,
                         cudaFuncAttributeMaxDynamicSharedMemorySize, smem_bytes);

    repack<<<dim3(64, 16), 256>>>(WU_w);
    prep_misc<<<16, 256>>>(WU_w, WU_b);
    init_state<<<(Bb * Hh + 255) / 256, 256>>>(z0, c_z0);

    lstm_persist<<<128, 256, smem_bytes>>>(rnn_input, tau, alpha_w, alpha_b,
                                           Wx_w, Wx_b, out);

    finalize<<<(Bb * Zz + 127) / 128, 128>>>(c_z0, out);
}